// round 15
// baseline (speedup 1.0000x reference)
#include <cuda_runtime.h>

// NeRF fine sampling — persistent grid-stride version of the R14 kernel.
//   inputs : rays_o [N,3], rays_d [N,3], z_vals [N,64] (sorted), weights [N,64]
//   outputs: pts [N,192,3], z_all [N,192]  (d_out = [pts | z_all])

#define NS        64
#define NI        128
#define NALL      192
#define RPB       8
#define FULLMASK  0xffffffffu
#define INV127    (1.0f / 127.0f)

// per-warp smem layout (floats)
#define OFF_CDF   0     // 64  (cdf[0..62], [63]=+INF sentinel)
#define OFF_MZ    64    // 128 (float2[64]: mid, z)
#define OFF_ALL   192   // 192 (16B aligned)
#define STRIDE    384

// count of a[0..62] <= v, result in [0,63]; 6 probes, no fixup (n = 2^6-1)
__device__ __forceinline__ int cnt_le_63(const float* __restrict__ a, float v) {
    int pos = 0;
    #pragma unroll
    for (int step = 32; step >= 1; step >>= 1)
        if (a[pos + step - 1] <= v) pos += step;
    return pos;
}

// first sample index s with u_s = s*INV127 >= c (branchless 1-step fixup)
__device__ __forceinline__ int u_lo(float c) {
    int s = (int)ceilf(c * 127.0f);
    s = max(0, min(s, 128));
    s += (s < 128 && (float)s * INV127 < c) ? 1 : 0;
    s -= (s > 0 && (float)(s - 1) * INV127 >= c) ? 1 : 0;
    return s;
}

// bitmask of lanes [lo, hi), 0 <= lo <= hi <= 32
__device__ __forceinline__ unsigned lane_range_mask(int lo, int hi) {
    const unsigned mh = (hi >= 32) ? 0xffffffffu : ((1u << hi) - 1u);
    const unsigned ml = (lo >= 32) ? 0xffffffffu : ((1u << lo) - 1u);
    return mh & ~ml;
}

__global__ __launch_bounds__(256, 7)
void nerf_fine_sample_kernel(
    const float* __restrict__ rays_o,
    const float* __restrict__ rays_d,
    const float* __restrict__ z_vals,
    const float* __restrict__ weights,
    float* __restrict__ out_pts,   // [N,192,3]
    float* __restrict__ out_z,     // [N,192]
    int n_rays,
    int write_pts,
    int write_z)
{
    __shared__ float smem[RPB * STRIDE];

    const int warp = threadIdx.x >> 5;
    const int lane = threadIdx.x & 31;
    const int ray_stride = gridDim.x * RPB;

    float*  base  = smem + warp * STRIDE;
    float*  s_cdf = base + OFF_CDF;
    float2* s_mz  = (float2*)(base + OFF_MZ);
    float*  s_all = base + OFF_ALL;

    for (int ray = blockIdx.x * RPB + warp; ray < n_rays; ray += ray_stride) {

    // ---- loads ---------------------------------------------------------
    const float* zr = z_vals + (size_t)ray * NS;
    const float z0 = zr[lane];          // z[lane]
    const float z1 = zr[lane + 32];     // z[lane+32]

    // weights as aligned float2: f2 = (w[2l], w[2l+1])
    const float2 f2 = ((const float2*)(weights + (size_t)ray * NS))[lane];

    // ---- pair-scan over 31 pairs (single 5-round scan) -----------------
    // pair l (l=0..30) covers w'[2l+1], w'[2l+2]  (w' = w + 1e-5)
    const float xn = __shfl_down_sync(FULLMASK, f2.x, 1);   // w[2l+2] (l31 self)
    const float p  = (lane < 31) ? (f2.y + 1e-5f) : 0.0f;   // w'[2l+1]
    const float q  = (lane < 31) ? (xn   + 1e-5f) : 0.0f;   // w'[2l+2]
    float S = p + q;                                         // pair sum
    #pragma unroll
    for (int off = 1; off < 32; off <<= 1) {
        float v = __shfl_up_sync(FULLMASK, S, off);
        if (lane >= off) S += v;
    }
    const float wsum = __shfl_sync(FULLMASK, S, 31);         // total of w'[1..62]
    const float inv  = 1.0f / wsum;

    // cdf[j] = prefix(w'[1..j]) * inv.
    const int   llo   = lane >> 1;                            // j = lane
    const float S_lm1 = __shfl_sync(FULLMASK, S, (llo + 31) & 31);
    const float p_lo  = __shfl_sync(FULLMASK, p, llo);
    const float pref_lo = ((llo == 0) ? 0.0f : S_lm1) + ((lane & 1) ? p_lo : 0.0f);
    const float cdf_lo  = pref_lo * inv;                      // cdf[lane]

    const int   lhi   = llo + 16;                             // j = lane + 32
    const float S_hm1 = __shfl_sync(FULLMASK, S, lhi - 1);
    const float p_hi  = __shfl_sync(FULLMASK, p, lhi);
    float cdf_hi = (S_hm1 + ((lane & 1) ? p_hi : 0.0f)) * inv; // cdf[lane+32]

    // ---- mids from z (all shuffles unconditional) ----------------------
    const float zn0 = __shfl_down_sync(FULLMASK, z0, 1);   // z[lane+1] (l31 self)
    const float z32 = __shfl_sync(FULLMASK, z1, 0);        // z[32]
    const float zn1 = __shfl_down_sync(FULLMASK, z1, 1);   // z[lane+33] (l31 self)
    const float mid_lo = 0.5f * (z0 + ((lane == 31) ? z32 : zn0));  // mid[lane]
    float mid_hi = 0.5f * (z1 + zn1);                               // mid[lane+32]
    const float mid62 = __shfl_sync(FULLMASK, mid_hi, 30);          // mid[62]
    if (lane == 31) {
        cdf_hi = __int_as_float(0x7f800000);  // +INF sentinel at cdf[63]
        mid_hi = mid62;                       // finite pad at mid[63]
    }

    s_cdf[lane]      = cdf_lo;
    s_cdf[lane + 32] = cdf_hi;
    s_mz[lane]       = make_float2(mid_lo, z0);
    s_mz[lane + 32]  = make_float2(mid_hi, z1);

    // ---- bin-start table in registers: st[lane], st[lane+32] -----------
    const int st_lo = u_lo(cdf_lo);                          // st[lane]
    const int st_hi = (lane == 31) ? 128 : u_lo(cdf_hi);     // st[lane+32]
    const int st_lo_up = __shfl_up_sync(FULLMASK, st_lo, 1); // st[lane-1]
    const int st_hi_up = __shfl_up_sync(FULLMASK, st_hi, 1); // st[lane+31]
    const int st31     = __shfl_sync(FULLMASK, st_lo, 31);   // st[31]
    const int Sp0 = (lane == 0) ? 0    : st_lo_up;
    const int Sp1 = (lane == 0) ? st31 : st_hi_up;
    __syncwarp();

    // ---- sampling: lane owns samples 4*lane .. 4*lane+3 ----------------
    // ballot words: bw[t] bit L = (v < z[k+1]) for sample 4L+t
    unsigned bw[4];
    {
        const int   s0 = 4 * lane;
        const float u0 = (float)s0 * INV127;

        int k = cnt_le_63(s_cdf, u0) - 1;       // bin of sample s0 (0..62)
        float  cl  = s_cdf[k];
        float  ch  = s_cdf[k + 1];
        float  ml  = s_mz[k].x;
        float2 mzh = s_mz[k + 1];
        float  mh  = mzh.x, zn = mzh.y;

        #pragma unroll
        for (int t = 0; t < 4; t++) {
            const float u = (float)(s0 + t) * INV127;
            while (ch <= u) {                   // INF sentinel caps k at 62
                k++;
                cl = ch; ml = mh;
                ch  = s_cdf[k + 1];
                mzh = s_mz[k + 1];
                mh = mzh.x; zn = mzh.y;
            }
            const float den  = ch - cl;         // INF at k==62 -> rden = 0
            const float rden = (den < 1e-5f) ? 1.0f : __fdividef(1.0f, den);
            const float v    = fmaf((u - cl) * rden, mh - ml, ml);
            const int before_z = (v < zn) ? 1 : 0;
            bw[t] = __ballot_sync(FULLMASK, before_z != 0);
            const int r = (s0 + t) + k + 1 + (1 - before_z);
            s_all[r] = v;
        }
    }
    __syncwarp();

    // ---- place z_vals: rank = i + st[i-1] + popc(bits in bin i-1) ------
    #pragma unroll
    for (int t2 = 0; t2 < 2; t2++) {
        const int   i  = lane + 32 * t2;
        const float zi = t2 ? z1 : z0;
        const int Sp = t2 ? Sp1 : Sp0;          // st[i-1]
        const int Sc = t2 ? st_hi : st_lo;      // st[i]
        int cnt = 0;
        #pragma unroll
        for (int t = 0; t < 4; t++) {
            const int lo = max(0, (Sp - t + 3) >> 2);
            const int hi = max(0, (Sc - t + 3) >> 2);
            cnt += __popc(bw[t] & lane_range_mask(lo, hi));
        }
        s_all[i + Sp + cnt] = zi;
    }
    __syncwarp();

    // ---- outputs: vectorized float4 streaming stores -------------------
    const float ox = rays_o[ray * 3 + 0];
    const float oy = rays_o[ray * 3 + 1];
    const float oz = rays_o[ray * 3 + 2];
    const float dx = rays_d[ray * 3 + 0];
    const float dy = rays_d[ray * 3 + 1];
    const float dz = rays_d[ray * 3 + 2];

    if (write_pts) {
        float4* po4 = (float4*)(out_pts + (size_t)ray * (NALL * 3));
        // incremental sample index / phase: e0 = 4*(lane+32t); s0 = e0/3; r = e0%3
        int s0 = (4 * lane) / 3;
        int r  = 4 * lane - 3 * s0;
        #pragma unroll
        for (int t = 0; t < 5; t++) {
            const int pI = lane + 32 * t;       // float4 index, 144 total
            if (t < 4 || lane < 16) {
                const float zv0 = s_all[s0];
                const float zv1 = s_all[s0 + 1];
                const float p0x = fmaf(dx, zv0, ox);
                const float p0y = fmaf(dy, zv0, oy);
                const float p0z = fmaf(dz, zv0, oz);
                const float p1x = fmaf(dx, zv1, ox);
                const float p1y = fmaf(dy, zv1, oy);
                const float p1z = fmaf(dz, zv1, oz);
                float4 v;
                v.x = (r == 0) ? p0x : ((r == 1) ? p0y : p0z);
                v.y = (r == 0) ? p0y : ((r == 1) ? p0z : p1x);
                v.z = (r == 0) ? p0z : ((r == 1) ? p1x : p1y);
                v.w = (r == 0) ? p1x : ((r == 1) ? p1y : p1z);
                __stcs(po4 + pI, v);
            }
            // advance by 128 output elements: 128 = 3*42 + 2
            s0 += 42; r += 2;
            if (r >= 3) { r -= 3; s0 += 1; }
        }
    }

    if (write_z) {
        float4* zo4 = (float4*)(out_z + (size_t)ray * NALL);
        const float4* sa4 = (const float4*)s_all;
        #pragma unroll
        for (int t = 0; t < 2; t++) {
            const int qI = lane + 32 * t;       // 48 float4
            if (t == 0 || lane < 16)
                __stcs(zo4 + qI, sa4[qI]);
        }
    }
    __syncwarp();   // next iteration rewrites s_all

    } // ray loop
}

extern "C" void kernel_launch(void* const* d_in, const int* in_sizes, int n_in,
                              void* d_out, int out_size)
{
    const float* rays_o  = (const float*)d_in[0];
    const float* rays_d  = (const float*)d_in[1];
    const float* z_vals  = (const float*)d_in[2];
    const float* weights = (const float*)d_in[3];

    const int n_rays = in_sizes[0] / 3;

    const long long pts_elems = (long long)n_rays * NALL * 3;
    const long long z_elems   = (long long)n_rays * NALL;

    const int write_pts = (out_size >= pts_elems) ? 1 : 0;
    const int write_z   = (out_size >= pts_elems + z_elems) ? 1 : 0;

    float* out_pts = (float*)d_out;
    float* out_z   = out_pts + pts_elems;

    // persistent: one wave of 7 blocks/SM on 148 SMs
    int nblk = 148 * 7;
    const int work_blk = (n_rays + RPB - 1) / RPB;
    if (work_blk < nblk) nblk = work_blk;

    nerf_fine_sample_kernel<<<nblk, 256>>>(
        rays_o, rays_d, z_vals, weights, out_pts, out_z, n_rays,
        write_pts, write_z);
}

// round 16
// speedup vs baseline: 1.2016x; 1.2016x over previous
#include <cuda_runtime.h>

// NeRF fine sampling — hybrid search+walk, ballot-based z-placement,
// register bin-start table, 6-probe search, early ray o/d loads.
//   inputs : rays_o [N,3], rays_d [N,3], z_vals [N,64] (sorted), weights [N,64]
//   outputs: pts [N,192,3], z_all [N,192]  (d_out = [pts | z_all])

#define NS        64
#define NI        128
#define NALL      192
#define RPB       8
#define FULLMASK  0xffffffffu
#define INV127    (1.0f / 127.0f)

// per-warp smem layout (floats)
#define OFF_CDF   0     // 64  (cdf[0..62], [63]=+INF sentinel)
#define OFF_MZ    64    // 128 (float2[64]: mid, z)
#define OFF_ALL   192   // 192 (16B aligned)
#define STRIDE    384

// count of a[0..62] <= v, result in [0,63]; 6 probes, no fixup (n = 2^6-1)
__device__ __forceinline__ int cnt_le_63(const float* __restrict__ a, float v) {
    int pos = 0;
    #pragma unroll
    for (int step = 32; step >= 1; step >>= 1)
        if (a[pos + step - 1] <= v) pos += step;
    return pos;
}

// first sample index s with u_s = s*INV127 >= c (branchless 1-step fixup)
__device__ __forceinline__ int u_lo(float c) {
    int s = (int)ceilf(c * 127.0f);
    s = max(0, min(s, 128));
    s += (s < 128 && (float)s * INV127 < c) ? 1 : 0;
    s -= (s > 0 && (float)(s - 1) * INV127 >= c) ? 1 : 0;
    return s;
}

// bitmask of lanes [lo, hi), 0 <= lo <= hi <= 32
__device__ __forceinline__ unsigned lane_range_mask(int lo, int hi) {
    const unsigned mh = (hi >= 32) ? 0xffffffffu : ((1u << hi) - 1u);
    const unsigned ml = (lo >= 32) ? 0xffffffffu : ((1u << lo) - 1u);
    return mh & ~ml;
}

__global__ __launch_bounds__(256, 7)
void nerf_fine_sample_kernel(
    const float* __restrict__ rays_o,
    const float* __restrict__ rays_d,
    const float* __restrict__ z_vals,
    const float* __restrict__ weights,
    float* __restrict__ out_pts,   // [N,192,3]
    float* __restrict__ out_z,     // [N,192]
    int n_rays,
    int write_pts,
    int write_z)
{
    __shared__ float smem[RPB * STRIDE];

    const int warp = threadIdx.x >> 5;
    const int lane = threadIdx.x & 31;
    const int ray  = blockIdx.x * RPB + warp;
    if (ray >= n_rays) return;

    float*  base  = smem + warp * STRIDE;
    float*  s_cdf = base + OFF_CDF;
    float2* s_mz  = (float2*)(base + OFF_MZ);
    float*  s_all = base + OFF_ALL;

    // ---- early loads (overlap DRAM latency with the scan chain) --------
    const float ox = rays_o[ray * 3 + 0];
    const float oy = rays_o[ray * 3 + 1];
    const float oz = rays_o[ray * 3 + 2];
    const float dx = rays_d[ray * 3 + 0];
    const float dy = rays_d[ray * 3 + 1];
    const float dz = rays_d[ray * 3 + 2];

    const float* zr = z_vals + (size_t)ray * NS;
    const float z0 = zr[lane];          // z[lane]
    const float z1 = zr[lane + 32];     // z[lane+32]

    const float* wr = weights + (size_t)ray * NS;
    float a = wr[1 + lane] + 1e-5f;                          // w[0..31]
    float b = (lane < 30) ? (wr[33 + lane] + 1e-5f) : 0.0f;  // w[32..61]

    // ---- inclusive scan over 62 weights --------------------------------
    #pragma unroll
    for (int off = 1; off < 32; off <<= 1) {
        float v = __shfl_up_sync(FULLMASK, a, off);
        if (lane >= off) a += v;
    }
    const float totA = __shfl_sync(FULLMASK, a, 31);
    #pragma unroll
    for (int off = 1; off < 32; off <<= 1) {
        float v = __shfl_up_sync(FULLMASK, b, off);
        if (lane >= off) b += v;
    }
    b += totA;
    const float wsum = __shfl_sync(FULLMASK, b, 31);
    const float inv  = 1.0f / wsum;

    // ---- register build of cdf/mid (all shuffles unconditional) --------
    const float au  = __shfl_up_sync(FULLMASK, a, 1);      // a[lane-1]
    const float bu  = __shfl_up_sync(FULLMASK, b, 1);      // b[lane-1]
    const float a31 = __shfl_sync(FULLMASK, a, 31);
    const float zn0 = __shfl_down_sync(FULLMASK, z0, 1);   // z[lane+1] (l31 self)
    const float z32 = __shfl_sync(FULLMASK, z1, 0);        // z[32]
    const float zn1 = __shfl_down_sync(FULLMASK, z1, 1);   // z[lane+33] (l31 self)

    const float cdf_lo = (lane == 0) ? 0.0f : au * inv;             // cdf[lane]
    float cdf_hi = (lane == 0) ? a31 * inv : bu * inv;              // cdf[lane+32]
    const float mid_lo = 0.5f * (z0 + ((lane == 31) ? z32 : zn0));  // mid[lane]
    float mid_hi = 0.5f * (z1 + zn1);                               // mid[lane+32]
    const float mid62 = __shfl_sync(FULLMASK, mid_hi, 30);          // mid[62]
    if (lane == 31) {
        cdf_hi = __int_as_float(0x7f800000);  // +INF sentinel at cdf[63]
        mid_hi = mid62;                       // finite pad at mid[63]
    }

    s_cdf[lane]      = cdf_lo;
    s_cdf[lane + 32] = cdf_hi;
    s_mz[lane]       = make_float2(mid_lo, z0);
    s_mz[lane + 32]  = make_float2(mid_hi, z1);

    // ---- bin-start table in registers: st[lane], st[lane+32] -----------
    const int st_lo = u_lo(cdf_lo);                          // st[lane]
    const int st_hi = (lane == 31) ? 128 : u_lo(cdf_hi);     // st[lane+32]
    const int st_lo_up = __shfl_up_sync(FULLMASK, st_lo, 1); // st[lane-1]
    const int st_hi_up = __shfl_up_sync(FULLMASK, st_hi, 1); // st[lane+31]
    const int st31     = __shfl_sync(FULLMASK, st_lo, 31);   // st[31]
    const int Sp0 = (lane == 0) ? 0    : st_lo_up;
    const int Sp1 = (lane == 0) ? st31 : st_hi_up;
    __syncwarp();

    // ---- sampling: lane owns samples 4*lane .. 4*lane+3 ----------------
    // ballot words: bw[t] bit L = (v < z[k+1]) for sample 4L+t
    unsigned bw[4];
    {
        const int   s0 = 4 * lane;
        const float u0 = (float)s0 * INV127;

        int k = cnt_le_63(s_cdf, u0) - 1;       // bin of sample s0 (0..62)
        float  cl  = s_cdf[k];
        float  ch  = s_cdf[k + 1];
        float  ml  = s_mz[k].x;
        float2 mzh = s_mz[k + 1];
        float  mh  = mzh.x, zn = mzh.y;

        #pragma unroll
        for (int t = 0; t < 4; t++) {
            const float u = (float)(s0 + t) * INV127;
            while (ch <= u) {                   // INF sentinel caps k at 62
                k++;
                cl = ch; ml = mh;
                ch  = s_cdf[k + 1];
                mzh = s_mz[k + 1];
                mh = mzh.x; zn = mzh.y;
            }
            const float den  = ch - cl;         // INF at k==62 -> rden = 0
            const float rden = (den < 1e-5f) ? 1.0f : __fdividef(1.0f, den);
            const float v    = fmaf((u - cl) * rden, mh - ml, ml);
            const int before_z = (v < zn) ? 1 : 0;
            bw[t] = __ballot_sync(FULLMASK, before_z != 0);
            const int r = (s0 + t) + k + 1 + (1 - before_z);
            s_all[r] = v;
        }
    }
    __syncwarp();

    // ---- place z_vals: rank = i + st[i-1] + popc(bits in bin i-1) ------
    #pragma unroll
    for (int t2 = 0; t2 < 2; t2++) {
        const int   i  = lane + 32 * t2;
        const float zi = t2 ? z1 : z0;
        const int Sp = t2 ? Sp1 : Sp0;          // st[i-1]
        const int Sc = t2 ? st_hi : st_lo;      // st[i]
        int cnt = 0;
        #pragma unroll
        for (int t = 0; t < 4; t++) {
            const int lo = max(0, (Sp - t + 3) >> 2);
            const int hi = max(0, (Sc - t + 3) >> 2);
            cnt += __popc(bw[t] & lane_range_mask(lo, hi));
        }
        s_all[i + Sp + cnt] = zi;
    }
    __syncwarp();

    // ---- outputs: vectorized float4 streaming stores -------------------
    if (write_pts) {
        float4* po4 = (float4*)(out_pts + (size_t)ray * (NALL * 3));
        // incremental sample index / phase: e0 = 4*(lane+32t); s0 = e0/3; r = e0%3
        int s0 = (4 * lane) / 3;
        int r  = 4 * lane - 3 * s0;
        #pragma unroll
        for (int t = 0; t < 5; t++) {
            const int pI = lane + 32 * t;       // float4 index, 144 total
            if (t < 4 || lane < 16) {
                const float zv0 = s_all[s0];
                const float zv1 = s_all[s0 + 1];
                const float p0x = fmaf(dx, zv0, ox);
                const float p0y = fmaf(dy, zv0, oy);
                const float p0z = fmaf(dz, zv0, oz);
                const float p1x = fmaf(dx, zv1, ox);
                const float p1y = fmaf(dy, zv1, oy);
                const float p1z = fmaf(dz, zv1, oz);
                float4 v;
                v.x = (r == 0) ? p0x : ((r == 1) ? p0y : p0z);
                v.y = (r == 0) ? p0y : ((r == 1) ? p0z : p1x);
                v.z = (r == 0) ? p0z : ((r == 1) ? p1x : p1y);
                v.w = (r == 0) ? p1x : ((r == 1) ? p1y : p1z);
                __stcs(po4 + pI, v);
            }
            // advance by 128 output elements: 128 = 3*42 + 2
            s0 += 42; r += 2;
            if (r >= 3) { r -= 3; s0 += 1; }
        }
    }

    if (write_z) {
        float4* zo4 = (float4*)(out_z + (size_t)ray * NALL);
        const float4* sa4 = (const float4*)s_all;
        #pragma unroll
        for (int t = 0; t < 2; t++) {
            const int qI = lane + 32 * t;       // 48 float4
            if (t == 0 || lane < 16)
                __stcs(zo4 + qI, sa4[qI]);
        }
    }
}

extern "C" void kernel_launch(void* const* d_in, const int* in_sizes, int n_in,
                              void* d_out, int out_size)
{
    const float* rays_o  = (const float*)d_in[0];
    const float* rays_d  = (const float*)d_in[1];
    const float* z_vals  = (const float*)d_in[2];
    const float* weights = (const float*)d_in[3];

    const int n_rays = in_sizes[0] / 3;

    const long long pts_elems = (long long)n_rays * NALL * 3;
    const long long z_elems   = (long long)n_rays * NALL;

    const int write_pts = (out_size >= pts_elems) ? 1 : 0;
    const int write_z   = (out_size >= pts_elems + z_elems) ? 1 : 0;

    float* out_pts = (float*)d_out;
    float* out_z   = out_pts + pts_elems;

    dim3 grid((n_rays + RPB - 1) / RPB);
    nerf_fine_sample_kernel<<<grid, 256>>>(
        rays_o, rays_d, z_vals, weights, out_pts, out_z, n_rays,
        write_pts, write_z);
}

// round 17
// speedup vs baseline: 1.3089x; 1.0893x over previous
#include <cuda_runtime.h>

// NeRF fine sampling — hybrid search+walk, ballot z-placement, register st
// table, TMA bulk stores for both outputs (pts staged in smem, fixed-pattern
// 3-float4-per-4-samples expansion, no phase selects).
//   inputs : rays_o [N,3], rays_d [N,3], z_vals [N,64] (sorted), weights [N,64]
//   outputs: pts [N,192,3], z_all [N,192]  (d_out = [pts | z_all])

#define NS        64
#define NI        128
#define NALL      192
#define RPB       8
#define FULLMASK  0xffffffffu
#define INV127    (1.0f / 127.0f)

// per-warp smem layout (floats)
#define OFF_CDF   0     // 64  (cdf[0..62], [63]=+INF sentinel)
#define OFF_MZ    64    // 128 (float2[64]: mid, z)
#define OFF_ALL   192   // 192 (768B, 16B aligned)
#define OFF_PTS   384   // 576 (2304B, 16B aligned)
#define STRIDE    960   // floats per warp (3840B, 16B aligned)

// count of a[0..62] <= v, result in [0,63]; 6 probes, no fixup (n = 2^6-1)
__device__ __forceinline__ int cnt_le_63(const float* __restrict__ a, float v) {
    int pos = 0;
    #pragma unroll
    for (int step = 32; step >= 1; step >>= 1)
        if (a[pos + step - 1] <= v) pos += step;
    return pos;
}

// first sample index s with u_s = s*INV127 >= c (branchless 1-step fixup)
__device__ __forceinline__ int u_lo(float c) {
    int s = (int)ceilf(c * 127.0f);
    s = max(0, min(s, 128));
    s += (s < 128 && (float)s * INV127 < c) ? 1 : 0;
    s -= (s > 0 && (float)(s - 1) * INV127 >= c) ? 1 : 0;
    return s;
}

// bitmask of lanes [lo, hi), 0 <= lo <= hi <= 32
__device__ __forceinline__ unsigned lane_range_mask(int lo, int hi) {
    const unsigned mh = (hi >= 32) ? 0xffffffffu : ((1u << hi) - 1u);
    const unsigned ml = (lo >= 32) ? 0xffffffffu : ((1u << lo) - 1u);
    return mh & ~ml;
}

__global__ __launch_bounds__(256, 7)
void nerf_fine_sample_kernel(
    const float* __restrict__ rays_o,
    const float* __restrict__ rays_d,
    const float* __restrict__ z_vals,
    const float* __restrict__ weights,
    float* __restrict__ out_pts,   // [N,192,3]
    float* __restrict__ out_z,     // [N,192]
    int n_rays,
    int write_pts,
    int write_z)
{
    __shared__ __align__(16) float smem[RPB * STRIDE];

    const int warp = threadIdx.x >> 5;
    const int lane = threadIdx.x & 31;
    const int ray  = blockIdx.x * RPB + warp;
    if (ray >= n_rays) return;

    float*  base   = smem + warp * STRIDE;
    float*  s_cdf  = base + OFF_CDF;
    float2* s_mz   = (float2*)(base + OFF_MZ);
    float*  s_all  = base + OFF_ALL;
    float4* s_pts4 = (float4*)(base + OFF_PTS);

    // ---- early loads (overlap DRAM latency with the scan chain) --------
    const float ox = rays_o[ray * 3 + 0];
    const float oy = rays_o[ray * 3 + 1];
    const float oz = rays_o[ray * 3 + 2];
    const float dx = rays_d[ray * 3 + 0];
    const float dy = rays_d[ray * 3 + 1];
    const float dz = rays_d[ray * 3 + 2];

    const float* zr = z_vals + (size_t)ray * NS;
    const float z0 = zr[lane];          // z[lane]
    const float z1 = zr[lane + 32];     // z[lane+32]

    const float* wr = weights + (size_t)ray * NS;
    float a = wr[1 + lane] + 1e-5f;                          // w[0..31]
    float b = (lane < 30) ? (wr[33 + lane] + 1e-5f) : 0.0f;  // w[32..61]

    // ---- inclusive scan over 62 weights --------------------------------
    #pragma unroll
    for (int off = 1; off < 32; off <<= 1) {
        float v = __shfl_up_sync(FULLMASK, a, off);
        if (lane >= off) a += v;
    }
    const float totA = __shfl_sync(FULLMASK, a, 31);
    #pragma unroll
    for (int off = 1; off < 32; off <<= 1) {
        float v = __shfl_up_sync(FULLMASK, b, off);
        if (lane >= off) b += v;
    }
    b += totA;
    const float wsum = __shfl_sync(FULLMASK, b, 31);
    const float inv  = 1.0f / wsum;

    // ---- register build of cdf/mid (all shuffles unconditional) --------
    const float au  = __shfl_up_sync(FULLMASK, a, 1);      // a[lane-1]
    const float bu  = __shfl_up_sync(FULLMASK, b, 1);      // b[lane-1]
    const float a31 = __shfl_sync(FULLMASK, a, 31);
    const float zn0 = __shfl_down_sync(FULLMASK, z0, 1);   // z[lane+1] (l31 self)
    const float z32 = __shfl_sync(FULLMASK, z1, 0);        // z[32]
    const float zn1 = __shfl_down_sync(FULLMASK, z1, 1);   // z[lane+33] (l31 self)

    const float cdf_lo = (lane == 0) ? 0.0f : au * inv;             // cdf[lane]
    float cdf_hi = (lane == 0) ? a31 * inv : bu * inv;              // cdf[lane+32]
    const float mid_lo = 0.5f * (z0 + ((lane == 31) ? z32 : zn0));  // mid[lane]
    float mid_hi = 0.5f * (z1 + zn1);                               // mid[lane+32]
    const float mid62 = __shfl_sync(FULLMASK, mid_hi, 30);          // mid[62]
    if (lane == 31) {
        cdf_hi = __int_as_float(0x7f800000);  // +INF sentinel at cdf[63]
        mid_hi = mid62;                       // finite pad at mid[63]
    }

    s_cdf[lane]      = cdf_lo;
    s_cdf[lane + 32] = cdf_hi;
    s_mz[lane]       = make_float2(mid_lo, z0);
    s_mz[lane + 32]  = make_float2(mid_hi, z1);

    // ---- bin-start table in registers: st[lane], st[lane+32] -----------
    const int st_lo = u_lo(cdf_lo);                          // st[lane]
    const int st_hi = (lane == 31) ? 128 : u_lo(cdf_hi);     // st[lane+32]
    const int st_lo_up = __shfl_up_sync(FULLMASK, st_lo, 1); // st[lane-1]
    const int st_hi_up = __shfl_up_sync(FULLMASK, st_hi, 1); // st[lane+31]
    const int st31     = __shfl_sync(FULLMASK, st_lo, 31);   // st[31]
    const int Sp0 = (lane == 0) ? 0    : st_lo_up;
    const int Sp1 = (lane == 0) ? st31 : st_hi_up;
    __syncwarp();

    // ---- sampling: lane owns samples 4*lane .. 4*lane+3 ----------------
    // ballot words: bw[t] bit L = (v < z[k+1]) for sample 4L+t
    unsigned bw[4];
    {
        const int   s0 = 4 * lane;
        const float u0 = (float)s0 * INV127;

        int k = cnt_le_63(s_cdf, u0) - 1;       // bin of sample s0 (0..62)
        float  cl  = s_cdf[k];
        float  ch  = s_cdf[k + 1];
        float  ml  = s_mz[k].x;
        float2 mzh = s_mz[k + 1];
        float  mh  = mzh.x, zn = mzh.y;

        #pragma unroll
        for (int t = 0; t < 4; t++) {
            const float u = (float)(s0 + t) * INV127;
            while (ch <= u) {                   // INF sentinel caps k at 62
                k++;
                cl = ch; ml = mh;
                ch  = s_cdf[k + 1];
                mzh = s_mz[k + 1];
                mh = mzh.x; zn = mzh.y;
            }
            const float den  = ch - cl;         // INF at k==62 -> rden = 0
            const float rden = (den < 1e-5f) ? 1.0f : __fdividef(1.0f, den);
            const float v    = fmaf((u - cl) * rden, mh - ml, ml);
            const int before_z = (v < zn) ? 1 : 0;
            bw[t] = __ballot_sync(FULLMASK, before_z != 0);
            const int r = (s0 + t) + k + 1 + (1 - before_z);
            s_all[r] = v;
        }
    }
    __syncwarp();

    // ---- place z_vals: rank = i + st[i-1] + popc(bits in bin i-1) ------
    #pragma unroll
    for (int t2 = 0; t2 < 2; t2++) {
        const int   i  = lane + 32 * t2;
        const float zi = t2 ? z1 : z0;
        const int Sp = t2 ? Sp1 : Sp0;          // st[i-1]
        const int Sc = t2 ? st_hi : st_lo;      // st[i]
        int cnt = 0;
        #pragma unroll
        for (int t = 0; t < 4; t++) {
            const int lo = max(0, (Sp - t + 3) >> 2);
            const int hi = max(0, (Sc - t + 3) >> 2);
            cnt += __popc(bw[t] & lane_range_mask(lo, hi));
        }
        s_all[i + Sp + cnt] = zi;
    }
    __syncwarp();

    // ---- pts expansion: unit j reads sa4[j] -> 3 float4 (fixed pattern)
    {
        const float4* sa4 = (const float4*)s_all;
        #pragma unroll
        for (int t = 0; t < 2; t++) {
            const int j = lane + 32 * t;        // 48 units
            if (t == 0 || lane < 16) {
                const float4 zq = sa4[j];
                float4 f0, f1, f2;
                f0.x = fmaf(dx, zq.x, ox); f0.y = fmaf(dy, zq.x, oy);
                f0.z = fmaf(dz, zq.x, oz); f0.w = fmaf(dx, zq.y, ox);
                f1.x = fmaf(dy, zq.y, oy); f1.y = fmaf(dz, zq.y, oz);
                f1.z = fmaf(dx, zq.z, ox); f1.w = fmaf(dy, zq.z, oy);
                f2.x = fmaf(dz, zq.z, oz); f2.y = fmaf(dx, zq.w, ox);
                f2.z = fmaf(dy, zq.w, oy); f2.w = fmaf(dz, zq.w, oz);
                s_pts4[3 * j + 0] = f0;
                s_pts4[3 * j + 1] = f1;
                s_pts4[3 * j + 2] = f2;
            }
        }
    }
    __syncwarp();

    // ---- TMA bulk stores: smem -> gmem (per-warp, elected lane) --------
    if (lane == 0) {
        asm volatile("fence.proxy.async.shared::cta;" ::: "memory");
        const unsigned pts_saddr =
            (unsigned)__cvta_generic_to_shared(base + OFF_PTS);
        const unsigned all_saddr =
            (unsigned)__cvta_generic_to_shared(s_all);
        if (write_pts) {
            float* dst = out_pts + (size_t)ray * (NALL * 3);
            asm volatile(
                "cp.async.bulk.global.shared::cta.bulk_group [%0], [%1], %2;"
                :: "l"(dst), "r"(pts_saddr), "r"(NALL * 3 * 4) : "memory");
        }
        if (write_z) {
            float* dst = out_z + (size_t)ray * NALL;
            asm volatile(
                "cp.async.bulk.global.shared::cta.bulk_group [%0], [%1], %2;"
                :: "l"(dst), "r"(all_saddr), "r"(NALL * 4) : "memory");
        }
        asm volatile("cp.async.bulk.commit_group;" ::: "memory");
        asm volatile("cp.async.bulk.wait_group 0;" ::: "memory");
    }
}

extern "C" void kernel_launch(void* const* d_in, const int* in_sizes, int n_in,
                              void* d_out, int out_size)
{
    const float* rays_o  = (const float*)d_in[0];
    const float* rays_d  = (const float*)d_in[1];
    const float* z_vals  = (const float*)d_in[2];
    const float* weights = (const float*)d_in[3];

    const int n_rays = in_sizes[0] / 3;

    const long long pts_elems = (long long)n_rays * NALL * 3;
    const long long z_elems   = (long long)n_rays * NALL;

    const int write_pts = (out_size >= pts_elems) ? 1 : 0;
    const int write_z   = (out_size >= pts_elems + z_elems) ? 1 : 0;

    float* out_pts = (float*)d_out;
    float* out_z   = out_pts + pts_elems;

    dim3 grid((n_rays + RPB - 1) / RPB);
    nerf_fine_sample_kernel<<<grid, 256>>>(
        rays_o, rays_d, z_vals, weights, out_pts, out_z, n_rays,
        write_pts, write_z);
}